// round 2
// baseline (speedup 1.0000x reference)
#include <cuda_runtime.h>
#include <math.h>

#define BDIM 4
#define CDIM 64
#define IDIM 32
#define LDIM 4096

#define BM 128
#define BN 32

typedef unsigned long long u64;

// ---- packed f32x2 helpers (Blackwell fma.rn.f32x2 — ptxas never auto-emits) ----
__device__ __forceinline__ u64 ffma2(u64 a, u64 b, u64 c) {
    u64 d;
    asm("fma.rn.f32x2 %0, %1, %2, %3;" : "=l"(d) : "l"(a), "l"(b), "l"(c));
    return d;
}
__device__ __forceinline__ u64 fmul2(u64 a, u64 b) {
    u64 d;
    asm("mul.rn.f32x2 %0, %1, %2;" : "=l"(d) : "l"(a), "l"(b));
    return d;
}
__device__ __forceinline__ u64 pack2(float lo, float hi) {
    u64 d;
    asm("mov.b64 %0, {%1, %2};" : "=l"(d) : "f"(lo), "f"(hi));
    return d;
}
__device__ __forceinline__ float2 unpack2(u64 a) {
    float2 r;
    asm("mov.b64 {%0, %1}, %2;" : "=f"(r.x), "=f"(r.y) : "l"(a));
    return r;
}

// scratch (allocation-free rule: __device__ globals)
__device__ float d_theta[BDIM * LDIM * IDIM];
__device__ float d_phi[BDIM * LDIM * IDIM];
__device__ float d_g[BDIM * LDIM * IDIM];
__device__ float d_y[BDIM * LDIM * IDIM];

// ---------------------------------------------------------------------------
// Kernel 1: channel projections  x[B,C,L] -> theta/phi/g  stored [B,L,32]
// ---------------------------------------------------------------------------
__global__ __launch_bounds__(256) void proj_kernel(
    const float* __restrict__ x,
    const float* __restrict__ g_w, const float* __restrict__ g_b,
    const float* __restrict__ th_w, const float* __restrict__ th_b,
    const float* __restrict__ ph_w, const float* __restrict__ ph_b)
{
    const int b  = blockIdx.y;
    const int l0 = blockIdx.x * 128;
    const int t  = threadIdx.x;

    __shared__ float xs[CDIM][128];       // x tile, [c][l]
    __shared__ float wsT[3][CDIM][IDIM];  // transposed weights [proj][c][o]
    __shared__ float bs[3][IDIM];

    const float* xb = x + (size_t)b * CDIM * LDIM + l0;
    for (int idx = t; idx < CDIM * 128; idx += 256) {
        int c = idx >> 7, l = idx & 127;
        xs[c][l] = xb[(size_t)c * LDIM + l];
    }
    for (int idx = t; idx < CDIM * IDIM; idx += 256) {
        int o = idx >> 6;   // idx = o*64 + c
        int c = idx & 63;
        wsT[0][c][o] = g_w[idx];
        wsT[1][c][o] = th_w[idx];
        wsT[2][c][o] = ph_w[idx];
    }
    if (t < IDIM) { bs[0][t] = g_b[t]; bs[1][t] = th_b[t]; bs[2][t] = ph_b[t]; }
    __syncthreads();

    const int o  = t & 31;
    const int lg = t >> 5;  // 0..7
    for (int i = 0; i < 16; ++i) {
        const int l = lg + (i << 3);
        float sg0 = 0.f, sg1 = 0.f, st0 = 0.f, st1 = 0.f, sp0 = 0.f, sp1 = 0.f;
#pragma unroll
        for (int c = 0; c < CDIM; c += 2) {
            float x0 = xs[c][l], x1 = xs[c + 1][l];
            sg0 = fmaf(wsT[0][c][o],     x0, sg0);
            sg1 = fmaf(wsT[0][c + 1][o], x1, sg1);
            st0 = fmaf(wsT[1][c][o],     x0, st0);
            st1 = fmaf(wsT[1][c + 1][o], x1, st1);
            sp0 = fmaf(wsT[2][c][o],     x0, sp0);
            sp1 = fmaf(wsT[2][c + 1][o], x1, sp1);
        }
        size_t oidx = ((size_t)b * LDIM + l0 + l) * IDIM + o;
        d_g[oidx]     = sg0 + sg1 + bs[0][o];
        d_theta[oidx] = st0 + st1 + bs[1][o];
        d_phi[oidx]   = sp0 + sp1 + bs[2][o];
    }
}

// ---------------------------------------------------------------------------
// Kernel 2: flash attention with packed f32x2 math.
// 256 threads: 0..127 -> keys [0,2048), 128..255 -> keys [2048,4096),
// same 128 queries; partial softmax states merged at the end.
// ---------------------------------------------------------------------------
__global__ __launch_bounds__(256) void flash_kernel()
{
    const int b  = blockIdx.y;
    const int q0 = blockIdx.x * BM;
    const int t  = threadIdx.x;
    const int h  = t >> 7;    // key-half
    const int lt = t & 127;   // query index within tile

    __shared__ __align__(16) u64 Ks[2][BN][16];
    __shared__ __align__(16) u64 Vs[2][BN][16];
    __shared__ __align__(16) u64 stAcc[BM][17];  // padded
    __shared__ float stM[BM];
    __shared__ float stL[BM];

    // load Q row into packed registers (pairs are contiguous -> free packing)
    u64 q2[16];
    const ulonglong2* Qp = (const ulonglong2*)(d_theta + ((size_t)b * LDIM + q0 + lt) * IDIM);
#pragma unroll
    for (int i = 0; i < 8; ++i) { ulonglong2 v = Qp[i]; q2[2*i] = v.x; q2[2*i+1] = v.y; }

    u64 acc[16];
#pragma unroll
    for (int i = 0; i < 16; ++i) acc[i] = 0ull;  // two packed +0.0f
    float m = -INFINITY, lsum = 0.f;

    const int HALFK = LDIM / 2;
    const float* Kb = d_phi + ((size_t)b * LDIM + (size_t)h * HALFK) * IDIM;
    const float* Vb = d_g   + ((size_t)b * LDIM + (size_t)h * HALFK) * IDIM;

    float4* KsH = (float4*)Ks[h];
    float4* VsH = (float4*)Vs[h];

    for (int kt = 0; kt < HALFK; kt += BN) {
        const float4* Kg = (const float4*)(Kb + (size_t)kt * IDIM);
        const float4* Vg = (const float4*)(Vb + (size_t)kt * IDIM);
        KsH[lt]       = Kg[lt];
        KsH[lt + 128] = Kg[lt + 128];
        VsH[lt]       = Vg[lt];
        VsH[lt + 128] = Vg[lt + 128];
        asm volatile("bar.sync %0, %1;" :: "r"(1 + h), "r"(128) : "memory");

        // ---- scores: 16 FFMA2 per key (was 32 FFMA) ----
        float sc[BN];
#pragma unroll
        for (int j = 0; j < BN; ++j) {
            u64 s0 = 0ull, s1 = 0ull;
            const ulonglong2* Kj = (const ulonglong2*)Ks[h][j];
#pragma unroll
            for (int dd = 0; dd < 8; ++dd) {
                ulonglong2 kv = Kj[dd];
                s0 = ffma2(q2[2*dd],     kv.x, s0);
                s1 = ffma2(q2[2*dd + 1], kv.y, s1);
            }
            float2 a = unpack2(s0), c = unpack2(s1);
            sc[j] = (a.x + a.y) + (c.x + c.y);
        }

        // ---- online softmax update ----
        float tmax = sc[0];
#pragma unroll
        for (int j = 1; j < BN; ++j) tmax = fmaxf(tmax, sc[j]);
        float mnew = fmaxf(m, tmax);
        float corr = __expf(m - mnew);
        m = mnew;
        lsum *= corr;
        u64 cc = pack2(corr, corr);
#pragma unroll
        for (int i = 0; i < 16; ++i) acc[i] = fmul2(acc[i], cc);
        float ps = 0.f;
#pragma unroll
        for (int j = 0; j < BN; ++j) {
            float p = __expf(sc[j] - mnew);
            sc[j] = p;
            ps += p;
        }
        lsum += ps;

        // ---- P @ V: 16 FFMA2 per key (was 32 FFMA) ----
#pragma unroll
        for (int j = 0; j < BN; ++j) {
            u64 pp = pack2(sc[j], sc[j]);
            const ulonglong2* Vj = (const ulonglong2*)Vs[h][j];
#pragma unroll
            for (int dd = 0; dd < 8; ++dd) {
                ulonglong2 vv = Vj[dd];
                acc[2*dd]     = ffma2(pp, vv.x, acc[2*dd]);
                acc[2*dd + 1] = ffma2(pp, vv.y, acc[2*dd + 1]);
            }
        }
        asm volatile("bar.sync %0, %1;" :: "r"(1 + h), "r"(128) : "memory");
    }

    // ---- merge the two key-halves ----
    __syncthreads();
    if (h == 1) {
        stM[lt] = m;
        stL[lt] = lsum;
#pragma unroll
        for (int i = 0; i < 16; ++i) stAcc[lt][i] = acc[i];
    }
    __syncthreads();
    if (h == 0) {
        float m2 = stM[lt], l2 = stL[lt];
        float mn = fmaxf(m, m2);
        float c1 = __expf(m - mn);
        float c2 = __expf(m2 - mn);
        float inv = 1.f / (lsum * c1 + l2 * c2);
        u64 c1i = pack2(c1 * inv, c1 * inv);
        u64 c2i = pack2(c2 * inv, c2 * inv);
        u64* Yp = (u64*)(d_y + ((size_t)b * LDIM + q0 + lt) * IDIM);
#pragma unroll
        for (int i = 0; i < 16; ++i) {
            u64 r = fmul2(acc[i], c1i);
            Yp[i] = ffma2(stAcc[lt][i], c2i, r);
        }
    }
}

// ---------------------------------------------------------------------------
// Kernel 3: out[b,c,l] = sum_o W_w[c,o] * y[b,l,o] + W_b[c] + x[b,c,l]
// ---------------------------------------------------------------------------
__global__ __launch_bounds__(256) void out_kernel(
    const float* __restrict__ x,
    const float* __restrict__ W_w, const float* __restrict__ W_b,
    float* __restrict__ out)
{
    const int b  = blockIdx.y;
    const int l0 = blockIdx.x * 128;
    const int t  = threadIdx.x;

    __shared__ __align__(16) float ys[128][36];  // padded rows
    __shared__ float wt[CDIM][IDIM];
    __shared__ float wb[CDIM];

    const float4* Yg = (const float4*)(d_y + ((size_t)b * LDIM + l0) * IDIM);
    for (int idx = t; idx < 128 * 8; idx += 256) {
        int r = idx >> 3, cpos = idx & 7;
        ((float4*)ys[r])[cpos] = Yg[idx];
    }
    for (int idx = t; idx < CDIM * IDIM; idx += 256)
        ((float*)wt)[idx] = W_w[idx];
    if (t < CDIM) wb[t] = W_b[t];
    __syncthreads();

    for (int idx = t; idx < CDIM * 128; idx += 256) {
        int c = idx >> 7, l = idx & 127;
        float s0 = wb[c], s1 = 0.f;
#pragma unroll
        for (int o = 0; o < IDIM; o += 2) {
            s0 = fmaf(wt[c][o],     ys[l][o],     s0);
            s1 = fmaf(wt[c][o + 1], ys[l][o + 1], s1);
        }
        size_t gi = ((size_t)b * CDIM + c) * LDIM + l0 + l;
        out[gi] = s0 + s1 + x[gi];
    }
}

// ---------------------------------------------------------------------------
extern "C" void kernel_launch(void* const* d_in, const int* in_sizes, int n_in,
                              void* d_out, int out_size)
{
    const float* x    = (const float*)d_in[0];
    const float* g_w  = (const float*)d_in[1];
    const float* g_b  = (const float*)d_in[2];
    const float* th_w = (const float*)d_in[3];
    const float* th_b = (const float*)d_in[4];
    const float* ph_w = (const float*)d_in[5];
    const float* ph_b = (const float*)d_in[6];
    const float* W_w  = (const float*)d_in[7];
    const float* W_b  = (const float*)d_in[8];
    float* out = (float*)d_out;

    dim3 gp(LDIM / 128, BDIM);
    proj_kernel<<<gp, 256>>>(x, g_w, g_b, th_w, th_b, ph_w, ph_b);

    dim3 gf(LDIM / BM, BDIM);
    flash_kernel<<<gf, 256>>>();

    dim3 go(LDIM / 128, BDIM);
    out_kernel<<<go, 256>>>(x, W_w, W_b, out);
}

// round 4
// speedup vs baseline: 3.6590x; 3.6590x over previous
#include <cuda_runtime.h>
#include <cuda_bf16.h>
#include <stdint.h>
#include <math.h>

#define BDIM 4
#define CDIM 64
#define IDIM 32
#define LDIM 4096

// ---------------- scratch (__device__ globals; allocation-free rule) --------
// rows are [hi32 | lo32] bf16 = 128 bytes per token
__device__ __align__(256) __nv_bfloat16 d_qhl[BDIM * LDIM * 64];
__device__ __align__(256) __nv_bfloat16 d_khl[BDIM * LDIM * 64];
__device__ __align__(256) __nv_bfloat16 d_vhl[BDIM * LDIM * 64];
__device__ float d_y[BDIM * LDIM * IDIM];

// ---------------- helpers ----------------
__device__ __forceinline__ uint32_t smem_u32(const void* p) {
    uint32_t a;
    asm("{ .reg .u64 t; cvta.to.shared.u64 t, %1; cvt.u32.u64 %0, t; }" : "=r"(a) : "l"(p));
    return a;
}
__device__ __forceinline__ void ldsm_x4(uint32_t a, uint32_t* r) {
    asm volatile("ldmatrix.sync.aligned.m8n8.x4.shared.b16 {%0,%1,%2,%3}, [%4];"
                 : "=r"(r[0]), "=r"(r[1]), "=r"(r[2]), "=r"(r[3]) : "r"(a));
}
__device__ __forceinline__ void ldsm_x2(uint32_t a, uint32_t* r) {
    asm volatile("ldmatrix.sync.aligned.m8n8.x2.shared.b16 {%0,%1}, [%2];"
                 : "=r"(r[0]), "=r"(r[1]) : "r"(a));
}
__device__ __forceinline__ void ldsm_x2t(uint32_t a, uint32_t* r) {
    asm volatile("ldmatrix.sync.aligned.m8n8.x2.trans.shared.b16 {%0,%1}, [%2];"
                 : "=r"(r[0]), "=r"(r[1]) : "r"(a));
}
__device__ __forceinline__ void mma_bf16(float* d, const uint32_t* a, const uint32_t* b) {
    asm volatile(
        "mma.sync.aligned.m16n8k16.row.col.f32.bf16.bf16.f32 "
        "{%0,%1,%2,%3}, {%4,%5,%6,%7}, {%8,%9}, {%0,%1,%2,%3};"
        : "+f"(d[0]), "+f"(d[1]), "+f"(d[2]), "+f"(d[3])
        : "r"(a[0]), "r"(a[1]), "r"(a[2]), "r"(a[3]), "r"(b[0]), "r"(b[1]));
}
__device__ __forceinline__ uint32_t cvt_bf16x2(float hi, float lo) {
    uint32_t d;
    asm("cvt.rn.bf16x2.f32 %0, %1, %2;" : "=r"(d) : "f"(hi), "f"(lo));
    return d;
}
#define SW(o) ((o) ^ (((o) >> 3) & 0x70))

// ---------------------------------------------------------------------------
// Kernel 1: projections -> bf16 hi/lo split operands, rows [hi32|lo32]
// ---------------------------------------------------------------------------
__global__ __launch_bounds__(256) void proj_kernel(
    const float* __restrict__ x,
    const float* __restrict__ g_w, const float* __restrict__ g_b,
    const float* __restrict__ th_w, const float* __restrict__ th_b,
    const float* __restrict__ ph_w, const float* __restrict__ ph_b)
{
    const int b  = blockIdx.y;
    const int l0 = blockIdx.x * 128;
    const int t  = threadIdx.x;

    __shared__ float xs[CDIM][128];
    __shared__ float wsT[3][CDIM][IDIM];
    __shared__ float bs[3][IDIM];

    const float* xb = x + (size_t)b * CDIM * LDIM + l0;
    for (int idx = t; idx < CDIM * 128; idx += 256) {
        int c = idx >> 7, l = idx & 127;
        xs[c][l] = xb[(size_t)c * LDIM + l];
    }
    for (int idx = t; idx < CDIM * IDIM; idx += 256) {
        int o = idx >> 6, c = idx & 63;
        wsT[0][c][o] = g_w[idx];
        wsT[1][c][o] = th_w[idx];
        wsT[2][c][o] = ph_w[idx];
    }
    if (t < IDIM) { bs[0][t] = g_b[t]; bs[1][t] = th_b[t]; bs[2][t] = ph_b[t]; }
    __syncthreads();

    const int o  = t & 31;
    const int lg = t >> 5;
    for (int i = 0; i < 16; ++i) {
        const int l = lg + (i << 3);
        float sg0 = 0.f, sg1 = 0.f, st0 = 0.f, st1 = 0.f, sp0 = 0.f, sp1 = 0.f;
#pragma unroll
        for (int c = 0; c < CDIM; c += 2) {
            float x0 = xs[c][l], x1 = xs[c + 1][l];
            sg0 = fmaf(wsT[0][c][o],     x0, sg0);
            sg1 = fmaf(wsT[0][c + 1][o], x1, sg1);
            st0 = fmaf(wsT[1][c][o],     x0, st0);
            st1 = fmaf(wsT[1][c + 1][o], x1, st1);
            sp0 = fmaf(wsT[2][c][o],     x0, sp0);
            sp1 = fmaf(wsT[2][c + 1][o], x1, sp1);
        }
        float gv = sg0 + sg1 + bs[0][o];
        float tv = st0 + st1 + bs[1][o];
        float pv = sp0 + sp1 + bs[2][o];

        __nv_bfloat16 th = __float2bfloat16(tv);
        __nv_bfloat16 tl = __float2bfloat16(tv - __bfloat162float(th));
        __nv_bfloat16 ph = __float2bfloat16(pv);
        __nv_bfloat16 pl = __float2bfloat16(pv - __bfloat162float(ph));
        __nv_bfloat16 gh = __float2bfloat16(gv);
        __nv_bfloat16 gl = __float2bfloat16(gv - __bfloat162float(gh));

        size_t rbase = ((size_t)b * LDIM + l0 + l) * 64;
        d_qhl[rbase + o]      = th;  d_qhl[rbase + 32 + o] = tl;
        d_khl[rbase + o]      = ph;  d_khl[rbase + 32 + o] = pl;
        d_vhl[rbase + o]      = gh;  d_vhl[rbase + 32 + o] = gl;
    }
}

// ---------------------------------------------------------------------------
// Kernel 2: flash attention via mma.sync bf16 (hi/lo split, no-max softmax)
// 256 threads (8 warps); warp w owns 16 query rows. grid = (32, 4).
// ---------------------------------------------------------------------------
__global__ __launch_bounds__(256, 1) void flash_mma_kernel()
{
    const int b   = blockIdx.y;
    const int q0  = blockIdx.x * 128;
    const int tid = threadIdx.x;
    const int w   = tid >> 5;
    const int l   = tid & 31;

    __shared__ __align__(1024) unsigned char smQ[128 * 128];      // 16KB
    __shared__ __align__(1024) unsigned char smKV[2][16384];      // 32KB (K rows 0-63, V rows 64-127)

    // ---- stage Q tile ----
    {
        const char* gQ = (const char*)d_qhl + (size_t)(b * LDIM + q0) * 128;
#pragma unroll
        for (int j = 0; j < 4; ++j) {
            uint32_t o = (uint32_t)tid * 64 + j * 16;
            uint4 v = *(const uint4*)(gQ + o);
            *(uint4*)(smQ + SW(o)) = v;
        }
    }
    __syncthreads();

    // ---- Q fragments (A operand, m16k16) ----
    uint32_t Qh[2][4], Ql[2][4];
    {
        const uint32_t qb  = smem_u32(smQ);
        const int row = 16 * w + (l & 7) + 8 * ((l >> 3) & 1);
        const int cb  = 16 * ((l >> 4) & 1);
#pragma unroll
        for (int ks = 0; ks < 2; ++ks) {
            uint32_t o = (uint32_t)row * 128 + ks * 32 + cb;
            ldsm_x4(qb + SW(o), Qh[ks]);
            uint32_t o2 = o + 64;
            ldsm_x4(qb + SW(o2), Ql[ks]);
        }
    }

    float Y[4][4];
#pragma unroll
    for (int n = 0; n < 4; ++n)
#pragma unroll
        for (int i = 0; i < 4; ++i) Y[n][i] = 0.f;
    float ls0 = 0.f, ls1 = 0.f;

    const int half = tid >> 7;                 // 0 = K loader, 1 = V loader
    const uint32_t off0 = (uint32_t)(tid & 127) * 64;
    const char* gsrc = (half ? (const char*)d_vhl : (const char*)d_khl) + (size_t)b * LDIM * 128;

    uint4 rg[4];
#pragma unroll
    for (int j = 0; j < 4; ++j)
        rg[j] = *(const uint4*)(gsrc + off0 + j * 16);

    for (int t = 0; t < 64; ++t) {
        unsigned char* buf = smKV[t & 1];
        // store prefetched tile
#pragma unroll
        for (int j = 0; j < 4; ++j) {
            uint32_t o = (uint32_t)half * 8192 + off0 + j * 16;
            *(uint4*)(buf + SW(o)) = rg[j];
        }
        __syncthreads();
        if (t < 63) {
            const char* p = gsrc + (size_t)(t + 1) * 64 * 128 + off0;
#pragma unroll
            for (int j = 0; j < 4; ++j)
                rg[j] = *(const uint4*)(p + j * 16);
        }

        const uint32_t kb = smem_u32(buf);

        // ---- S = Qhi.Khi + Qhi.Klo + Qlo.Khi ----
        float S[8][4];
#pragma unroll
        for (int n = 0; n < 8; ++n) {
#pragma unroll
            for (int i = 0; i < 4; ++i) S[n][i] = 0.f;
            uint32_t rowb = (uint32_t)(n * 8 + (l & 7)) * 128 + 16 * ((l >> 3) & 1);
            uint32_t kh0[2], kh1[2], kl0[2], kl1[2];
            ldsm_x2(kb + SW(rowb),      kh0);
            ldsm_x2(kb + SW(rowb + 32), kh1);
            ldsm_x2(kb + SW(rowb + 64), kl0);
            ldsm_x2(kb + SW(rowb + 96), kl1);
            mma_bf16(S[n], Qh[0], kh0);
            mma_bf16(S[n], Qh[1], kh1);
            mma_bf16(S[n], Qh[0], kl0);
            mma_bf16(S[n], Qh[1], kl1);
            mma_bf16(S[n], Ql[0], kh0);
            mma_bf16(S[n], Ql[1], kh1);
        }

        // ---- softmax numerator: exp + bf16 hi/lo split into P frags ----
        uint32_t Ph[4][4], Pl[4][4];
#pragma unroll
        for (int n = 0; n < 8; ++n) {
            float e0 = __expf(S[n][0]);
            float e1 = __expf(S[n][1]);
            float e2 = __expf(S[n][2]);
            float e3 = __expf(S[n][3]);
            ls0 += e0 + e1;
            ls1 += e2 + e3;
            uint32_t h01 = cvt_bf16x2(e1, e0);
            uint32_t h23 = cvt_bf16x2(e3, e2);
            float h0 = __uint_as_float(h01 << 16);
            float h1 = __uint_as_float(h01 & 0xFFFF0000u);
            float h2 = __uint_as_float(h23 << 16);
            float h3 = __uint_as_float(h23 & 0xFFFF0000u);
            uint32_t l01 = cvt_bf16x2(e1 - h1, e0 - h0);
            uint32_t l23 = cvt_bf16x2(e3 - h3, e2 - h2);
            const int kt = n >> 1, pos = (n & 1) * 2;
            Ph[kt][pos]     = h01;
            Ph[kt][pos + 1] = h23;
            Pl[kt][pos]     = l01;
            Pl[kt][pos + 1] = l23;
        }

        // ---- Y += Ph.Vh + Pl.Vh + Ph.Vl ----
#pragma unroll
        for (int kt = 0; kt < 4; ++kt) {
            uint32_t vrow = (uint32_t)(64 + kt * 16 + (l & 7) + 8 * ((l >> 3) & 1)) * 128;
#pragma unroll
            for (int n = 0; n < 4; ++n) {
                uint32_t vh[2], vl[2];
                ldsm_x2t(kb + SW(vrow + n * 16),      vh);
                ldsm_x2t(kb + SW(vrow + 64 + n * 16), vl);
                mma_bf16(Y[n], Ph[kt], vh);
                mma_bf16(Y[n], Pl[kt], vh);
                mma_bf16(Y[n], Ph[kt], vl);
            }
        }
    }

    // ---- reduce row sums within quads, normalize, store ----
    ls0 += __shfl_xor_sync(0xffffffffu, ls0, 1);
    ls0 += __shfl_xor_sync(0xffffffffu, ls0, 2);
    ls1 += __shfl_xor_sync(0xffffffffu, ls1, 1);
    ls1 += __shfl_xor_sync(0xffffffffu, ls1, 2);
    float inv0 = 1.f / ls0;
    float inv1 = 1.f / ls1;

    const int r0 = q0 + 16 * w + (l >> 2);
    const int dc = 2 * (l & 3);
#pragma unroll
    for (int n = 0; n < 4; ++n) {
        float2 v0 = make_float2(Y[n][0] * inv0, Y[n][1] * inv0);
        float2 v1 = make_float2(Y[n][2] * inv1, Y[n][3] * inv1);
        *(float2*)&d_y[((size_t)b * LDIM + r0) * 32 + n * 8 + dc]       = v0;
        *(float2*)&d_y[((size_t)b * LDIM + r0 + 8) * 32 + n * 8 + dc]   = v1;
    }
}

// ---------------------------------------------------------------------------
// Kernel 3: out[b,c,l] = sum_o W_w[c,o] * y[b,l,o] + W_b[c] + x[b,c,l]
// ---------------------------------------------------------------------------
__global__ __launch_bounds__(256) void out_kernel(
    const float* __restrict__ x,
    const float* __restrict__ W_w, const float* __restrict__ W_b,
    float* __restrict__ out)
{
    const int b  = blockIdx.y;
    const int l0 = blockIdx.x * 128;
    const int t  = threadIdx.x;

    __shared__ __align__(16) float ys[128][36];
    __shared__ float wt[CDIM][IDIM];
    __shared__ float wb[CDIM];

    const float4* Yg = (const float4*)(d_y + ((size_t)b * LDIM + l0) * IDIM);
    for (int idx = t; idx < 128 * 8; idx += 256) {
        int r = idx >> 3, cpos = idx & 7;
        ((float4*)ys[r])[cpos] = Yg[idx];
    }
    for (int idx = t; idx < CDIM * IDIM; idx += 256)
        ((float*)wt)[idx] = W_w[idx];
    if (t < CDIM) wb[t] = W_b[t];
    __syncthreads();

    for (int idx = t; idx < CDIM * 128; idx += 256) {
        int c = idx >> 7, l = idx & 127;
        float s0 = wb[c], s1 = 0.f;
#pragma unroll
        for (int o = 0; o < IDIM; o += 2) {
            s0 = fmaf(wt[c][o],     ys[l][o],     s0);
            s1 = fmaf(wt[c][o + 1], ys[l][o + 1], s1);
        }
        size_t gi = ((size_t)b * CDIM + c) * LDIM + l0 + l;
        out[gi] = s0 + s1 + x[gi];
    }
}

// ---------------------------------------------------------------------------
extern "C" void kernel_launch(void* const* d_in, const int* in_sizes, int n_in,
                              void* d_out, int out_size)
{
    const float* x    = (const float*)d_in[0];
    const float* g_w  = (const float*)d_in[1];
    const float* g_b  = (const float*)d_in[2];
    const float* th_w = (const float*)d_in[3];
    const float* th_b = (const float*)d_in[4];
    const float* ph_w = (const float*)d_in[5];
    const float* ph_b = (const float*)d_in[6];
    const float* W_w  = (const float*)d_in[7];
    const float* W_b  = (const float*)d_in[8];
    float* out = (float*)d_out;

    dim3 gp(LDIM / 128, BDIM);
    proj_kernel<<<gp, 256>>>(x, g_w, g_b, th_w, th_b, ph_w, ph_b);

    dim3 gf(LDIM / 128, BDIM);
    flash_mma_kernel<<<gf, 256>>>();

    dim3 go(LDIM / 128, BDIM);
    out_kernel<<<go, 256>>>(x, W_w, W_b, out);
}